// round 8
// baseline (speedup 1.0000x reference)
#include <cuda_runtime.h>
#include <cuda_bf16.h>
#include <math.h>

// Eikonal loss, single fused kernel, packed f32x2 arithmetic (sm_103a).
// One thread = 4x4 px item. 6 pred rows + 4 reach rows, independent loads,
// shfl halos. (B,1,H,W) = (64,1,512,512) fp32 -> 1 fp32 scalar.

#define H 512
#define W 512
#define W4 (W / 4)
#define THREADS 256
#define MAX_BLOCKS 16384

typedef unsigned long long u64;

__device__ float2 g_part[MAX_BLOCKS];
__device__ unsigned int g_ticket;   // zero-init at load; last block resets it

__device__ __forceinline__ float sqrt_approx(float x) {
    float r;
    asm("sqrt.approx.f32 %0, %1;" : "=f"(r) : "f"(x));
    return r;
}

// ---- packed f32x2 helpers ----
__device__ __forceinline__ u64 pk2(float lo, float hi) {
    u64 r; asm("mov.b64 %0, {%1, %2};" : "=l"(r) : "f"(lo), "f"(hi)); return r;
}
__device__ __forceinline__ void upk2(float& lo, float& hi, u64 v) {
    asm("mov.b64 {%0, %1}, %2;" : "=f"(lo), "=f"(hi) : "l"(v));
}
__device__ __forceinline__ u64 add2(u64 a, u64 b) {
    u64 r; asm("add.rn.f32x2 %0, %1, %2;" : "=l"(r) : "l"(a), "l"(b)); return r;
}
__device__ __forceinline__ u64 sub2(u64 a, u64 b) {
    u64 r; asm("sub.rn.f32x2 %0, %1, %2;" : "=l"(r) : "l"(a), "l"(b)); return r;
}
__device__ __forceinline__ u64 mul2(u64 a, u64 b) {
    u64 r; asm("mul.rn.f32x2 %0, %1, %2;" : "=l"(r) : "l"(a), "l"(b)); return r;
}
__device__ __forceinline__ u64 fma2(u64 a, u64 b, u64 c) {
    u64 r; asm("fma.rn.f32x2 %0, %1, %2, %3;" : "=l"(r) : "l"(a), "l"(b), "l"(c)); return r;
}

// Row features (UNSCALED): D = horizontal central diff, S = [1,2,1] row sum.
// Packed as (j=0,1) and (j=2,3) pairs.
__device__ __forceinline__ void row_sd(float4 v, const float* __restrict__ row,
                                       int x, int lane, u64 two2,
                                       u64& S01, u64& S23, u64& D01, u64& D23) {
    float wl = __shfl_up_sync(0xFFFFFFFFu, v.w, 1);
    float wr = __shfl_down_sync(0xFFFFFFFFu, v.x, 1);
    if (lane == 0)  wl = (x == 0)     ? v.x : __ldg(row + x - 1);
    if (lane == 31) wr = (x + 4 >= W) ? v.w : __ldg(row + x + 4);
    u64 P_lx = pk2(wl,  v.x);
    u64 P_xy = pk2(v.x, v.y);
    u64 P_yz = pk2(v.y, v.z);
    u64 P_zw = pk2(v.z, v.w);
    u64 P_wr = pk2(v.w, wr);
    D01 = sub2(P_yz, P_lx);                    // {vy-wl, vz-vx}
    D23 = sub2(P_wr, P_yz);                    // {vw-vy, wr-vz}
    S01 = fma2(P_xy, two2, add2(P_lx, P_yz));  // {wl+2vx+vy, vx+2vy+vz}
    S23 = fma2(P_zw, two2, add2(P_yz, P_wr));  // {vy+2vz+vw, vz+2vw+wr}
}

__global__ void __launch_bounds__(THREADS, 4) eik_fused_kernel(
    const float* __restrict__ pred,
    const float* __restrict__ reach,
    float* __restrict__ out,
    int nBlocks)
{
    const int gid  = blockIdx.x * THREADS + threadIdx.x;
    const int lane = threadIdx.x & 31;
    const int x4 = gid & (W4 - 1);
    const int yq = (gid >> 7) & (H / 4 - 1);
    const int b  = gid >> 14;

    const int x = x4 * 4;
    const int y = yq * 4;

    const size_t base = (size_t)b * (H * W);
    const float* p = pred + base;
    const float* r = reach + base;

    const float* pr0 = p + (size_t)((y > 0) ? (y - 1) : 0) * W;
    const float* pr1 = p + (size_t)y * W;
    const float* pr2 = pr1 + W;
    const float* pr3 = pr2 + W;
    const float* pr4 = pr3 + W;
    const float* pr5 = p + (size_t)((y + 4 < H) ? (y + 4) : (H - 1)) * W;

    // --- all loads independent, issued up-front ---
    float4 v0 = *(const float4*)(pr0 + x);
    float4 v1 = *(const float4*)(pr1 + x);
    float4 v2 = *(const float4*)(pr2 + x);
    float4 v3 = *(const float4*)(pr3 + x);
    float4 v4 = *(const float4*)(pr4 + x);
    float4 v5 = *(const float4*)(pr5 + x);
    float4 ra = __ldcs((const float4*)(r + (size_t)(y + 0) * W + x));
    float4 rb = __ldcs((const float4*)(r + (size_t)(y + 1) * W + x));
    float4 rc = __ldcs((const float4*)(r + (size_t)(y + 2) * W + x));
    float4 rd = __ldcs((const float4*)(r + (size_t)(y + 3) * W + x));

    const u64 two2 = pk2(2.0f, 2.0f);
    const u64 c64  = pk2(0.015625f, 0.015625f);  // (1/8)^2 scale fold
    const u64 eps2 = pk2(1e-8f, 1e-8f);

    u64 S01[6], S23[6], D01[6], D23[6];
    row_sd(v0, pr0, x, lane, two2, S01[0], S23[0], D01[0], D23[0]);
    row_sd(v1, pr1, x, lane, two2, S01[1], S23[1], D01[1], D23[1]);
    row_sd(v2, pr2, x, lane, two2, S01[2], S23[2], D01[2], D23[2]);
    row_sd(v3, pr3, x, lane, two2, S01[3], S23[3], D01[3], D23[3]);
    row_sd(v4, pr4, x, lane, two2, S01[4], S23[4], D01[4], D23[4]);
    row_sd(v5, pr5, x, lane, two2, S01[5], S23[5], D01[5], D23[5]);

    const float rv[4][4] = {{ra.x, ra.y, ra.z, ra.w},
                            {rb.x, rb.y, rb.z, rb.w},
                            {rc.x, rc.y, rc.z, rc.w},
                            {rd.x, rd.y, rd.z, rd.w}};

    float lsum = 0.0f;
    float lcnt = 0.0f;

    #pragma unroll
    for (int i = 0; i < 4; i++) {
        // packed Sobel combine (unscaled), then mag^2 = g2/64 + 1e-8
        u64 gx01 = fma2(D01[i + 1], two2, add2(D01[i], D01[i + 2]));
        u64 gx23 = fma2(D23[i + 1], two2, add2(D23[i], D23[i + 2]));
        u64 gy01 = sub2(S01[i + 2], S01[i]);
        u64 gy23 = sub2(S23[i + 2], S23[i]);
        u64 m01  = fma2(fma2(gx01, gx01, mul2(gy01, gy01)), c64, eps2);
        u64 m23  = fma2(fma2(gx23, gx23, mul2(gy23, gy23)), c64, eps2);

        float g[4];
        upk2(g[0], g[1], m01);
        upk2(g[2], g[3], m23);

        #pragma unroll
        for (int j = 0; j < 4; j++) {
            float viol = fabsf(sqrt_approx(g[j]) - 1.0f);
            if (rv[i][j] > 0.5f) {
                lsum += viol;
                lcnt += 1.0f;
            }
        }
    }

    // ---- block reduction (8 warps) ----
    #pragma unroll
    for (int off = 16; off > 0; off >>= 1) {
        lsum += __shfl_down_sync(0xFFFFFFFFu, lsum, off);
        lcnt += __shfl_down_sync(0xFFFFFFFFu, lcnt, off);
    }

    __shared__ float s_sum[8];
    __shared__ float s_cnt[8];
    const int wid = threadIdx.x >> 5;
    if (lane == 0) { s_sum[wid] = lsum; s_cnt[wid] = lcnt; }
    __syncthreads();

    __shared__ bool s_last;
    if (wid == 0) {
        lsum = (lane < 8) ? s_sum[lane] : 0.0f;
        lcnt = (lane < 8) ? s_cnt[lane] : 0.0f;
        #pragma unroll
        for (int off = 4; off > 0; off >>= 1) {
            lsum += __shfl_down_sync(0xFFFFFFFFu, lsum, off);
            lcnt += __shfl_down_sync(0xFFFFFFFFu, lcnt, off);
        }
        if (lane == 0) {
            g_part[blockIdx.x] = make_float2(lsum, lcnt);
            __threadfence();
            unsigned int prev = atomicAdd(&g_ticket, 1u);
            s_last = (prev == (unsigned int)(nBlocks - 1));
        }
    }
    __syncthreads();

    // ---- last block: reduce partials, write output, reset ticket ----
    if (s_last) {
        float fs = 0.0f, fc = 0.0f;
        for (int i = threadIdx.x; i < nBlocks; i += THREADS) {
            float2 v = g_part[i];
            fs += v.x;
            fc += v.y;
        }
        #pragma unroll
        for (int off = 16; off > 0; off >>= 1) {
            fs += __shfl_down_sync(0xFFFFFFFFu, fs, off);
            fc += __shfl_down_sync(0xFFFFFFFFu, fc, off);
        }
        if (lane == 0) { s_sum[wid] = fs; s_cnt[wid] = fc; }
        __syncthreads();
        if (threadIdx.x == 0) {
            fs = 0.0f; fc = 0.0f;
            #pragma unroll
            for (int i = 0; i < 8; i++) { fs += s_sum[i]; fc += s_cnt[i]; }
            out[0] = fs / fmaxf(fc, 1.0f);
            g_ticket = 0;   // reset for next graph replay
        }
    }
}

extern "C" void kernel_launch(void* const* d_in, const int* in_sizes, int n_in,
                              void* d_out, int out_size) {
    const float* pred  = (const float*)d_in[0];
    const float* reach = (const float*)d_in[1];
    float* out = (float*)d_out;

    const int total   = in_sizes[0];              // B*H*W
    const int nBlocks = (total / 16) / THREADS;   // 4096 for B=64

    eik_fused_kernel<<<nBlocks, THREADS>>>(pred, reach, out, nBlocks);
}

// round 9
// speedup vs baseline: 1.0632x; 1.0632x over previous
#include <cuda_runtime.h>
#include <cuda_bf16.h>
#include <math.h>

// Eikonal loss, single fused kernel. One thread = 4x8 px item (8 rows x 4 cols),
// two phases of 4 output rows sharing row features. Scalar math (f32x2 regressed),
// shfl halos, up-front independent pred loads, streaming reach loads.
// (B,1,H,W) = (64,1,512,512) fp32 -> 1 fp32 scalar.

#define H 512
#define W 512
#define W4 (W / 4)
#define THREADS 256
#define MAX_BLOCKS 16384

__device__ float2 g_part[MAX_BLOCKS];
__device__ unsigned int g_ticket;   // zero-init at load; last block resets it

__device__ __forceinline__ float sqrt_approx(float x) {
    float r;
    asm("sqrt.approx.f32 %0, %1;" : "=f"(r) : "f"(x));
    return r;
}

// Row features: D = scaled horizontal central diff, S = scaled [1,2,1] row sum.
__device__ __forceinline__ void row_sd(float4 v, const float* __restrict__ row,
                                       int x, int lane,
                                       float* __restrict__ S,
                                       float* __restrict__ D) {
    float wl = __shfl_up_sync(0xFFFFFFFFu, v.w, 1);
    float wr = __shfl_down_sync(0xFFFFFFFFu, v.x, 1);
    if (lane == 0)  wl = (x == 0)     ? v.x : __ldg(row + x - 1);
    if (lane == 31) wr = (x + 4 >= W) ? v.w : __ldg(row + x + 4);
    D[0] = (v.y - wl)  * 0.125f;
    D[1] = (v.z - v.x) * 0.125f;
    D[2] = (v.w - v.y) * 0.125f;
    D[3] = (wr  - v.z) * 0.125f;
    S[0] = fmaf(2.0f, v.x, wl  + v.y) * 0.125f;
    S[1] = fmaf(2.0f, v.y, v.x + v.z) * 0.125f;
    S[2] = fmaf(2.0f, v.z, v.y + v.w) * 0.125f;
    S[3] = fmaf(2.0f, v.w, v.z + wr ) * 0.125f;
}

// One output row from features (i-1, i, i+1) + reach vector.
__device__ __forceinline__ void out_row(const float* S0, const float* S1, const float* S2,
                                        const float* D0, const float* D1, const float* D2,
                                        float4 rr, float& lsum, float& lcnt) {
    const float rv[4] = {rr.x, rr.y, rr.z, rr.w};
    #pragma unroll
    for (int j = 0; j < 4; j++) {
        float gx = fmaf(2.0f, D1[j], D0[j] + D2[j]);
        float gy = S2[j] - S0[j];
        float g2 = fmaf(gx, gx, fmaf(gy, gy, 1e-8f));
        float viol = fabsf(sqrt_approx(g2) - 1.0f);
        float msk  = (rv[j] > 0.5f) ? 1.0f : 0.0f;
        lsum = fmaf(viol, msk, lsum);
        lcnt += msk;
    }
}

__global__ void __launch_bounds__(THREADS, 3) eik_fused_kernel(
    const float* __restrict__ pred,
    const float* __restrict__ reach,
    float* __restrict__ out,
    int nBlocks)
{
    const int gid  = blockIdx.x * THREADS + threadIdx.x;
    const int lane = threadIdx.x & 31;
    // gid -> (b, yo, x4): powers of two, bit ops only
    const int x4 = gid & (W4 - 1);
    const int yo = (gid >> 7) & (H / 8 - 1);
    const int b  = gid >> 13;

    const int x = x4 * 4;
    const int y = yo * 8;

    const size_t base = (size_t)b * (H * W);
    const float* p = pred + base;
    const float* r = reach + base;

    // 10 pred rows for 8 output rows: y-1 .. y+8 (edge-clamped)
    const float* pr0 = p + (size_t)((y > 0) ? (y - 1) : 0) * W;
    const float* pr1 = p + (size_t)y * W;
    const float* pr5 = pr1 + 4 * W;
    const float* pr9 = p + (size_t)((y + 8 < H) ? (y + 8) : (H - 1)) * W;

    // --- all pred loads independent, issued up-front ---
    float4 v0 = *(const float4*)(pr0 + x);
    float4 v1 = *(const float4*)(pr1 + x);
    float4 v2 = *(const float4*)(pr1 + W + x);
    float4 v3 = *(const float4*)(pr1 + 2 * W + x);
    float4 v4 = *(const float4*)(pr1 + 3 * W + x);
    float4 v5 = *(const float4*)(pr5 + x);
    float4 v6 = *(const float4*)(pr5 + W + x);
    float4 v7 = *(const float4*)(pr5 + 2 * W + x);
    float4 v8 = *(const float4*)(pr5 + 3 * W + x);
    float4 v9 = *(const float4*)(pr9 + x);

    float lsum = 0.0f;
    float lcnt = 0.0f;

    // ================= phase A: output rows y .. y+3 =================
    float4 ra0 = __ldcs((const float4*)(r + (size_t)(y + 0) * W + x));
    float4 ra1 = __ldcs((const float4*)(r + (size_t)(y + 1) * W + x));
    float4 ra2 = __ldcs((const float4*)(r + (size_t)(y + 2) * W + x));
    float4 ra3 = __ldcs((const float4*)(r + (size_t)(y + 3) * W + x));

    float S0[4], S1[4], S2[4], S3[4], S4[4], S5[4];
    float D0[4], D1[4], D2[4], D3[4], D4[4], D5[4];
    row_sd(v0, pr0,         x, lane, S0, D0);
    row_sd(v1, pr1,         x, lane, S1, D1);
    row_sd(v2, pr1 + W,     x, lane, S2, D2);
    row_sd(v3, pr1 + 2 * W, x, lane, S3, D3);
    row_sd(v4, pr1 + 3 * W, x, lane, S4, D4);
    row_sd(v5, pr5,         x, lane, S5, D5);

    out_row(S0, S1, S2, D0, D1, D2, ra0, lsum, lcnt);
    out_row(S1, S2, S3, D1, D2, D3, ra1, lsum, lcnt);
    out_row(S2, S3, S4, D2, D3, D4, ra2, lsum, lcnt);
    out_row(S3, S4, S5, D3, D4, D5, ra3, lsum, lcnt);

    // ================= phase B: output rows y+4 .. y+7 =================
    float4 rb0 = __ldcs((const float4*)(r + (size_t)(y + 4) * W + x));
    float4 rb1 = __ldcs((const float4*)(r + (size_t)(y + 5) * W + x));
    float4 rb2 = __ldcs((const float4*)(r + (size_t)(y + 6) * W + x));
    float4 rb3 = __ldcs((const float4*)(r + (size_t)(y + 7) * W + x));

    // reuse S4/S5 (rows y+3, y+4); overwrite S0..S3 with rows y+5..y+8
    row_sd(v6, pr5 + W,     x, lane, S0, D0);
    row_sd(v7, pr5 + 2 * W, x, lane, S1, D1);
    row_sd(v8, pr5 + 3 * W, x, lane, S2, D2);
    row_sd(v9, pr9,         x, lane, S3, D3);

    out_row(S4, S5, S0, D4, D5, D0, rb0, lsum, lcnt);
    out_row(S5, S0, S1, D5, D0, D1, rb1, lsum, lcnt);
    out_row(S0, S1, S2, D0, D1, D2, rb2, lsum, lcnt);
    out_row(S1, S2, S3, D1, D2, D3, rb3, lsum, lcnt);

    // ---- block reduction (8 warps) ----
    #pragma unroll
    for (int off = 16; off > 0; off >>= 1) {
        lsum += __shfl_down_sync(0xFFFFFFFFu, lsum, off);
        lcnt += __shfl_down_sync(0xFFFFFFFFu, lcnt, off);
    }

    __shared__ float s_sum[8];
    __shared__ float s_cnt[8];
    const int wid = threadIdx.x >> 5;
    if (lane == 0) { s_sum[wid] = lsum; s_cnt[wid] = lcnt; }
    __syncthreads();

    __shared__ bool s_last;
    if (wid == 0) {
        lsum = (lane < 8) ? s_sum[lane] : 0.0f;
        lcnt = (lane < 8) ? s_cnt[lane] : 0.0f;
        #pragma unroll
        for (int off = 4; off > 0; off >>= 1) {
            lsum += __shfl_down_sync(0xFFFFFFFFu, lsum, off);
            lcnt += __shfl_down_sync(0xFFFFFFFFu, lcnt, off);
        }
        if (lane == 0) {
            g_part[blockIdx.x] = make_float2(lsum, lcnt);
            __threadfence();
            unsigned int prev = atomicAdd(&g_ticket, 1u);
            s_last = (prev == (unsigned int)(nBlocks - 1));
        }
    }
    __syncthreads();

    // ---- last block: reduce partials, write output, reset ticket ----
    if (s_last) {
        float fs = 0.0f, fc = 0.0f;
        for (int i = threadIdx.x; i < nBlocks; i += THREADS) {
            float2 v = g_part[i];
            fs += v.x;
            fc += v.y;
        }
        #pragma unroll
        for (int off = 16; off > 0; off >>= 1) {
            fs += __shfl_down_sync(0xFFFFFFFFu, fs, off);
            fc += __shfl_down_sync(0xFFFFFFFFu, fc, off);
        }
        if (lane == 0) { s_sum[wid] = fs; s_cnt[wid] = fc; }
        __syncthreads();
        if (threadIdx.x == 0) {
            fs = 0.0f; fc = 0.0f;
            #pragma unroll
            for (int i = 0; i < 8; i++) { fs += s_sum[i]; fc += s_cnt[i]; }
            out[0] = fs / fmaxf(fc, 1.0f);
            g_ticket = 0;   // reset for next graph replay
        }
    }
}

extern "C" void kernel_launch(void* const* d_in, const int* in_sizes, int n_in,
                              void* d_out, int out_size) {
    const float* pred  = (const float*)d_in[0];
    const float* reach = (const float*)d_in[1];
    float* out = (float*)d_out;

    const int total   = in_sizes[0];              // B*H*W
    const int nBlocks = (total / 32) / THREADS;   // 2048 for B=64

    eik_fused_kernel<<<nBlocks, THREADS>>>(pred, reach, out, nBlocks);
}

// round 10
// speedup vs baseline: 1.0861x; 1.0215x over previous
#include <cuda_runtime.h>
#include <cuda_bf16.h>
#include <math.h>

// Eikonal loss, single fused kernel. One thread = 4x8 px item (8 rows x 4 cols),
// two phases of 4 output rows sharing row features. Unscaled S/D with scale
// folded into the epilogue fma. Shfl halos, up-front independent pred loads,
// streaming reach loads. (B,1,H,W) = (64,1,512,512) fp32 -> 1 fp32 scalar.

#define H 512
#define W 512
#define W4 (W / 4)
#define THREADS 256
#define MAX_BLOCKS 16384

__device__ float2 g_part[MAX_BLOCKS];
__device__ unsigned int g_ticket;   // zero-init at load; last block resets it

__device__ __forceinline__ float sqrt_approx(float x) {
    float r;
    asm("sqrt.approx.f32 %0, %1;" : "=f"(r) : "f"(x));
    return r;
}

// Row features (UNSCALED): D = horizontal central diff, S = [1,2,1] row sum.
__device__ __forceinline__ void row_sd(float4 v, const float* __restrict__ row,
                                       int x, int lane,
                                       float* __restrict__ S,
                                       float* __restrict__ D) {
    float wl = __shfl_up_sync(0xFFFFFFFFu, v.w, 1);
    float wr = __shfl_down_sync(0xFFFFFFFFu, v.x, 1);
    if (lane == 0)  wl = (x == 0)     ? v.x : __ldg(row + x - 1);
    if (lane == 31) wr = (x + 4 >= W) ? v.w : __ldg(row + x + 4);
    D[0] = v.y - wl;
    D[1] = v.z - v.x;
    D[2] = v.w - v.y;
    D[3] = wr  - v.z;
    S[0] = fmaf(2.0f, v.x, wl  + v.y);
    S[1] = fmaf(2.0f, v.y, v.x + v.z);
    S[2] = fmaf(2.0f, v.z, v.y + v.w);
    S[3] = fmaf(2.0f, v.w, v.z + wr );
}

// One output row from features (i-1, i, i+1) + reach vector.
// mag = sqrt(gx_u^2 + gy_u^2 + 64e-8) / 8  == sqrt((gx_u/8)^2 + (gy_u/8)^2 + 1e-8)
__device__ __forceinline__ void out_row(const float* S0, const float* S1, const float* S2,
                                        const float* D0, const float* D1, const float* D2,
                                        float4 rr, float& lsum, int& lcnt) {
    const float rv[4] = {rr.x, rr.y, rr.z, rr.w};
    #pragma unroll
    for (int j = 0; j < 4; j++) {
        float gx = fmaf(2.0f, D1[j], D0[j] + D2[j]);
        float gy = S2[j] - S0[j];
        float g2 = fmaf(gx, gx, fmaf(gy, gy, 6.4e-7f));
        float viol = fabsf(fmaf(sqrt_approx(g2), 0.125f, -1.0f));
        if (rv[j] > 0.5f) {
            lsum += viol;
            lcnt++;
        }
    }
}

__global__ void __launch_bounds__(THREADS, 3) eik_fused_kernel(
    const float* __restrict__ pred,
    const float* __restrict__ reach,
    float* __restrict__ out,
    int nBlocks)
{
    const int gid  = blockIdx.x * THREADS + threadIdx.x;
    const int lane = threadIdx.x & 31;
    // gid -> (b, yo, x4): powers of two, bit ops only
    const int x4 = gid & (W4 - 1);
    const int yo = (gid >> 7) & (H / 8 - 1);
    const int b  = gid >> 13;

    const int x = x4 * 4;
    const int y = yo * 8;

    const size_t base = (size_t)b * (H * W);
    const float* p = pred + base;
    const float* r = reach + base;

    // 10 pred rows for 8 output rows: y-1 .. y+8 (edge-clamped)
    const float* pr0 = p + (size_t)((y > 0) ? (y - 1) : 0) * W;
    const float* pr1 = p + (size_t)y * W;
    const float* pr5 = pr1 + 4 * W;
    const float* pr9 = p + (size_t)((y + 8 < H) ? (y + 8) : (H - 1)) * W;

    // --- all pred loads independent, issued up-front ---
    float4 v0 = *(const float4*)(pr0 + x);
    float4 v1 = *(const float4*)(pr1 + x);
    float4 v2 = *(const float4*)(pr1 + W + x);
    float4 v3 = *(const float4*)(pr1 + 2 * W + x);
    float4 v4 = *(const float4*)(pr1 + 3 * W + x);
    float4 v5 = *(const float4*)(pr5 + x);
    float4 v6 = *(const float4*)(pr5 + W + x);
    float4 v7 = *(const float4*)(pr5 + 2 * W + x);
    float4 v8 = *(const float4*)(pr5 + 3 * W + x);
    float4 v9 = *(const float4*)(pr9 + x);

    float lsum = 0.0f;
    int   lcnt = 0;

    // ================= phase A: output rows y .. y+3 =================
    float4 ra0 = __ldcs((const float4*)(r + (size_t)(y + 0) * W + x));
    float4 ra1 = __ldcs((const float4*)(r + (size_t)(y + 1) * W + x));
    float4 ra2 = __ldcs((const float4*)(r + (size_t)(y + 2) * W + x));
    float4 ra3 = __ldcs((const float4*)(r + (size_t)(y + 3) * W + x));

    float S0[4], S1[4], S2[4], S3[4], S4[4], S5[4];
    float D0[4], D1[4], D2[4], D3[4], D4[4], D5[4];
    row_sd(v0, pr0,         x, lane, S0, D0);
    row_sd(v1, pr1,         x, lane, S1, D1);
    row_sd(v2, pr1 + W,     x, lane, S2, D2);
    row_sd(v3, pr1 + 2 * W, x, lane, S3, D3);
    row_sd(v4, pr1 + 3 * W, x, lane, S4, D4);
    row_sd(v5, pr5,         x, lane, S5, D5);

    out_row(S0, S1, S2, D0, D1, D2, ra0, lsum, lcnt);
    out_row(S1, S2, S3, D1, D2, D3, ra1, lsum, lcnt);
    out_row(S2, S3, S4, D2, D3, D4, ra2, lsum, lcnt);
    out_row(S3, S4, S5, D3, D4, D5, ra3, lsum, lcnt);

    // ================= phase B: output rows y+4 .. y+7 =================
    float4 rb0 = __ldcs((const float4*)(r + (size_t)(y + 4) * W + x));
    float4 rb1 = __ldcs((const float4*)(r + (size_t)(y + 5) * W + x));
    float4 rb2 = __ldcs((const float4*)(r + (size_t)(y + 6) * W + x));
    float4 rb3 = __ldcs((const float4*)(r + (size_t)(y + 7) * W + x));

    // reuse S4/S5 (rows y+3, y+4); overwrite S0..S3 with rows y+5..y+8
    row_sd(v6, pr5 + W,     x, lane, S0, D0);
    row_sd(v7, pr5 + 2 * W, x, lane, S1, D1);
    row_sd(v8, pr5 + 3 * W, x, lane, S2, D2);
    row_sd(v9, pr9,         x, lane, S3, D3);

    out_row(S4, S5, S0, D4, D5, D0, rb0, lsum, lcnt);
    out_row(S5, S0, S1, D5, D0, D1, rb1, lsum, lcnt);
    out_row(S0, S1, S2, D0, D1, D2, rb2, lsum, lcnt);
    out_row(S1, S2, S3, D1, D2, D3, rb3, lsum, lcnt);

    // ---- block reduction (8 warps) ----
    float fcnt = (float)lcnt;
    #pragma unroll
    for (int off = 16; off > 0; off >>= 1) {
        lsum += __shfl_down_sync(0xFFFFFFFFu, lsum, off);
        fcnt += __shfl_down_sync(0xFFFFFFFFu, fcnt, off);
    }

    __shared__ float s_sum[8];
    __shared__ float s_cnt[8];
    const int wid = threadIdx.x >> 5;
    if (lane == 0) { s_sum[wid] = lsum; s_cnt[wid] = fcnt; }
    __syncthreads();

    __shared__ bool s_last;
    if (wid == 0) {
        lsum = (lane < 8) ? s_sum[lane] : 0.0f;
        fcnt = (lane < 8) ? s_cnt[lane] : 0.0f;
        #pragma unroll
        for (int off = 4; off > 0; off >>= 1) {
            lsum += __shfl_down_sync(0xFFFFFFFFu, lsum, off);
            fcnt += __shfl_down_sync(0xFFFFFFFFu, fcnt, off);
        }
        if (lane == 0) {
            g_part[blockIdx.x] = make_float2(lsum, fcnt);
            __threadfence();
            unsigned int prev = atomicAdd(&g_ticket, 1u);
            s_last = (prev == (unsigned int)(nBlocks - 1));
        }
    }
    __syncthreads();

    // ---- last block: reduce partials, write output, reset ticket ----
    if (s_last) {
        float fs = 0.0f, fc = 0.0f;
        for (int i = threadIdx.x; i < nBlocks; i += THREADS) {
            float2 v = g_part[i];
            fs += v.x;
            fc += v.y;
        }
        #pragma unroll
        for (int off = 16; off > 0; off >>= 1) {
            fs += __shfl_down_sync(0xFFFFFFFFu, fs, off);
            fc += __shfl_down_sync(0xFFFFFFFFu, fc, off);
        }
        if (lane == 0) { s_sum[wid] = fs; s_cnt[wid] = fc; }
        __syncthreads();
        if (threadIdx.x == 0) {
            fs = 0.0f; fc = 0.0f;
            #pragma unroll
            for (int i = 0; i < 8; i++) { fs += s_sum[i]; fc += s_cnt[i]; }
            out[0] = fs / fmaxf(fc, 1.0f);
            g_ticket = 0;   // reset for next graph replay
        }
    }
}

extern "C" void kernel_launch(void* const* d_in, const int* in_sizes, int n_in,
                              void* d_out, int out_size) {
    const float* pred  = (const float*)d_in[0];
    const float* reach = (const float*)d_in[1];
    float* out = (float*)d_out;

    const int total   = in_sizes[0];              // B*H*W
    const int nBlocks = (total / 32) / THREADS;   // 2048 for B=64

    eik_fused_kernel<<<nBlocks, THREADS>>>(pred, reach, out, nBlocks);
}

// round 11
// speedup vs baseline: 1.2515x; 1.1523x over previous
#include <cuda_runtime.h>
#include <cuda_bf16.h>
#include <math.h>

// Eikonal loss, single fused kernel. One thread = 4x8 px item (8 rows x 4 cols),
// two phases of 4 output rows sharing row features. Phase-local load batches
// (10-deep then 8-deep MLP) to cap register liveness at 4 blocks/SM.
// (B,1,H,W) = (64,1,512,512) fp32 -> 1 fp32 scalar.

#define H 512
#define W 512
#define W4 (W / 4)
#define THREADS 256
#define MAX_BLOCKS 16384

__device__ float2 g_part[MAX_BLOCKS];
__device__ unsigned int g_ticket;   // zero-init at load; last block resets it

__device__ __forceinline__ float sqrt_approx(float x) {
    float r;
    asm("sqrt.approx.f32 %0, %1;" : "=f"(r) : "f"(x));
    return r;
}

// Row features (UNSCALED): D = horizontal central diff, S = [1,2,1] row sum.
__device__ __forceinline__ void row_sd(float4 v, const float* __restrict__ row,
                                       int x, int lane,
                                       float* __restrict__ S,
                                       float* __restrict__ D) {
    float wl = __shfl_up_sync(0xFFFFFFFFu, v.w, 1);
    float wr = __shfl_down_sync(0xFFFFFFFFu, v.x, 1);
    if (lane == 0)  wl = (x == 0)     ? v.x : __ldg(row + x - 1);
    if (lane == 31) wr = (x + 4 >= W) ? v.w : __ldg(row + x + 4);
    D[0] = v.y - wl;
    D[1] = v.z - v.x;
    D[2] = v.w - v.y;
    D[3] = wr  - v.z;
    S[0] = fmaf(2.0f, v.x, wl  + v.y);
    S[1] = fmaf(2.0f, v.y, v.x + v.z);
    S[2] = fmaf(2.0f, v.z, v.y + v.w);
    S[3] = fmaf(2.0f, v.w, v.z + wr );
}

// One output row from features (i-1, i, i+1) + reach vector.
// mag = sqrt(gx_u^2 + gy_u^2 + 6.4e-7) * 0.125 == sqrt((gx_u/8)^2 + (gy_u/8)^2 + 1e-8)
__device__ __forceinline__ void out_row(const float* S0, const float* S1, const float* S2,
                                        const float* D0, const float* D1, const float* D2,
                                        float4 rr, float& lsum, int& lcnt) {
    const float rv[4] = {rr.x, rr.y, rr.z, rr.w};
    #pragma unroll
    for (int j = 0; j < 4; j++) {
        float gx = fmaf(2.0f, D1[j], D0[j] + D2[j]);
        float gy = S2[j] - S0[j];
        float g2 = fmaf(gx, gx, fmaf(gy, gy, 6.4e-7f));
        float viol = fabsf(fmaf(sqrt_approx(g2), 0.125f, -1.0f));
        if (rv[j] > 0.5f) {
            lsum += viol;
            lcnt++;
        }
    }
}

__global__ void __launch_bounds__(THREADS, 4) eik_fused_kernel(
    const float* __restrict__ pred,
    const float* __restrict__ reach,
    float* __restrict__ out,
    int nBlocks)
{
    const int gid  = blockIdx.x * THREADS + threadIdx.x;
    const int lane = threadIdx.x & 31;
    // gid -> (b, yo, x4): powers of two, bit ops only
    const int x4 = gid & (W4 - 1);
    const int yo = (gid >> 7) & (H / 8 - 1);
    const int b  = gid >> 13;

    const int x = x4 * 4;
    const int y = yo * 8;

    const size_t base = (size_t)b * (H * W);
    const float* p = pred + base;
    const float* r = reach + base;

    // pred rows: y-1 .. y+8 (edge-clamped)
    const float* pr0 = p + (size_t)((y > 0) ? (y - 1) : 0) * W;
    const float* pr1 = p + (size_t)y * W;
    const float* pr5 = pr1 + 4 * W;
    const float* pr9 = p + (size_t)((y + 8 < H) ? (y + 8) : (H - 1)) * W;

    float lsum = 0.0f;
    int   lcnt = 0;

    float S0[4], S1[4], S2[4], S3[4], S4[4], S5[4];
    float D0[4], D1[4], D2[4], D3[4], D4[4], D5[4];

    // ================= phase A: output rows y .. y+3 =================
    {
        // phase-A load batch: 6 pred + 4 reach, all independent
        float4 v0 = *(const float4*)(pr0 + x);
        float4 v1 = *(const float4*)(pr1 + x);
        float4 v2 = *(const float4*)(pr1 + W + x);
        float4 v3 = *(const float4*)(pr1 + 2 * W + x);
        float4 v4 = *(const float4*)(pr1 + 3 * W + x);
        float4 v5 = *(const float4*)(pr5 + x);
        float4 ra0 = __ldcs((const float4*)(r + (size_t)(y + 0) * W + x));
        float4 ra1 = __ldcs((const float4*)(r + (size_t)(y + 1) * W + x));
        float4 ra2 = __ldcs((const float4*)(r + (size_t)(y + 2) * W + x));
        float4 ra3 = __ldcs((const float4*)(r + (size_t)(y + 3) * W + x));

        row_sd(v0, pr0,         x, lane, S0, D0);
        row_sd(v1, pr1,         x, lane, S1, D1);
        row_sd(v2, pr1 + W,     x, lane, S2, D2);
        row_sd(v3, pr1 + 2 * W, x, lane, S3, D3);
        row_sd(v4, pr1 + 3 * W, x, lane, S4, D4);
        row_sd(v5, pr5,         x, lane, S5, D5);

        out_row(S0, S1, S2, D0, D1, D2, ra0, lsum, lcnt);
        out_row(S1, S2, S3, D1, D2, D3, ra1, lsum, lcnt);
        out_row(S2, S3, S4, D2, D3, D4, ra2, lsum, lcnt);
        out_row(S3, S4, S5, D3, D4, D5, ra3, lsum, lcnt);
    }

    // ================= phase B: output rows y+4 .. y+7 =================
    {
        // phase-B load batch: 4 pred + 4 reach
        float4 v6 = *(const float4*)(pr5 + W + x);
        float4 v7 = *(const float4*)(pr5 + 2 * W + x);
        float4 v8 = *(const float4*)(pr5 + 3 * W + x);
        float4 v9 = *(const float4*)(pr9 + x);
        float4 rb0 = __ldcs((const float4*)(r + (size_t)(y + 4) * W + x));
        float4 rb1 = __ldcs((const float4*)(r + (size_t)(y + 5) * W + x));
        float4 rb2 = __ldcs((const float4*)(r + (size_t)(y + 6) * W + x));
        float4 rb3 = __ldcs((const float4*)(r + (size_t)(y + 7) * W + x));

        // reuse S4/S5 (rows y+3, y+4); overwrite S0..S3 with rows y+5..y+8
        row_sd(v6, pr5 + W,     x, lane, S0, D0);
        row_sd(v7, pr5 + 2 * W, x, lane, S1, D1);
        row_sd(v8, pr5 + 3 * W, x, lane, S2, D2);
        row_sd(v9, pr9,         x, lane, S3, D3);

        out_row(S4, S5, S0, D4, D5, D0, rb0, lsum, lcnt);
        out_row(S5, S0, S1, D5, D0, D1, rb1, lsum, lcnt);
        out_row(S0, S1, S2, D0, D1, D2, rb2, lsum, lcnt);
        out_row(S1, S2, S3, D1, D2, D3, rb3, lsum, lcnt);
    }

    // ---- block reduction (8 warps) ----
    float fcnt = (float)lcnt;
    #pragma unroll
    for (int off = 16; off > 0; off >>= 1) {
        lsum += __shfl_down_sync(0xFFFFFFFFu, lsum, off);
        fcnt += __shfl_down_sync(0xFFFFFFFFu, fcnt, off);
    }

    __shared__ float s_sum[8];
    __shared__ float s_cnt[8];
    const int wid = threadIdx.x >> 5;
    if (lane == 0) { s_sum[wid] = lsum; s_cnt[wid] = fcnt; }
    __syncthreads();

    __shared__ bool s_last;
    if (wid == 0) {
        lsum = (lane < 8) ? s_sum[lane] : 0.0f;
        fcnt = (lane < 8) ? s_cnt[lane] : 0.0f;
        #pragma unroll
        for (int off = 4; off > 0; off >>= 1) {
            lsum += __shfl_down_sync(0xFFFFFFFFu, lsum, off);
            fcnt += __shfl_down_sync(0xFFFFFFFFu, fcnt, off);
        }
        if (lane == 0) {
            g_part[blockIdx.x] = make_float2(lsum, fcnt);
            __threadfence();
            unsigned int prev = atomicAdd(&g_ticket, 1u);
            s_last = (prev == (unsigned int)(nBlocks - 1));
        }
    }
    __syncthreads();

    // ---- last block: reduce partials, write output, reset ticket ----
    if (s_last) {
        float fs = 0.0f, fc = 0.0f;
        for (int i = threadIdx.x; i < nBlocks; i += THREADS) {
            float2 v = g_part[i];
            fs += v.x;
            fc += v.y;
        }
        #pragma unroll
        for (int off = 16; off > 0; off >>= 1) {
            fs += __shfl_down_sync(0xFFFFFFFFu, fs, off);
            fc += __shfl_down_sync(0xFFFFFFFFu, fc, off);
        }
        if (lane == 0) { s_sum[wid] = fs; s_cnt[wid] = fc; }
        __syncthreads();
        if (threadIdx.x == 0) {
            fs = 0.0f; fc = 0.0f;
            #pragma unroll
            for (int i = 0; i < 8; i++) { fs += s_sum[i]; fc += s_cnt[i]; }
            out[0] = fs / fmaxf(fc, 1.0f);
            g_ticket = 0;   // reset for next graph replay
        }
    }
}

extern "C" void kernel_launch(void* const* d_in, const int* in_sizes, int n_in,
                              void* d_out, int out_size) {
    const float* pred  = (const float*)d_in[0];
    const float* reach = (const float*)d_in[1];
    float* out = (float*)d_out;

    const int total   = in_sizes[0];              // B*H*W
    const int nBlocks = (total / 32) / THREADS;   // 2048 for B=64

    eik_fused_kernel<<<nBlocks, THREADS>>>(pred, reach, out, nBlocks);
}